// round 2
// baseline (speedup 1.0000x reference)
#include <cuda_runtime.h>

// AWBM bucket model as three parallel scans:
//   S_t = min(max(S_{t-1} + (p-e), 0), Smax)      -- clamp-add functions, closed under composition
//   excess_t = max(pre-clamp S - Smax, 0)
//   B_t affine in B_{t-1}:  B = k*(B + bfi*excess) -- affine (m,c), m const = k
//   total_t = (1-bfi)*e + (1-k)*(B_{t-1} + bfi*e)
//
// Pipeline: K1 per-chunk clamp composition -> K2 chunk-level S scan ->
//           K3 main pass (excess + partial totals + per-chunk affine) ->
//           K4 chunk-level B scan -> K5 tiny prefix correction (+ (1-k)*k^j*B_in).

#define CHUNK 8192
#define NTH 256
#define EPT (CHUNK / NTH)     // 32 elements per thread
#define MAX_CHUNKS 1024
#define SCAN_TH 1024

#define POS_INF __int_as_float(0x7f800000)
#define NEG_INF __int_as_float(0xff800000)

__device__ float g_fa[MAX_CHUNKS], g_fl[MAX_CHUNKS], g_fh[MAX_CHUNKS];
__device__ float g_Sin[MAX_CHUNKS];
__device__ float g_M[MAX_CHUNKS], g_C[MAX_CHUNKS];
__device__ float g_Bin[MAX_CHUNKS];

// ---------------------------------------------------------------------------
// K1: per-chunk composition of clamp functions f(x) = min(max(x+a, l), h)
// ---------------------------------------------------------------------------
__global__ void k1_chunk_fn(const float2* __restrict__ x, int T,
                            const float* __restrict__ psmax) {
    __shared__ float sd[CHUNK];
    __shared__ float sa[NTH], sl[NTH], sh[NTH];
    const float smax = psmax[0];
    const int chunk = blockIdx.x;
    const int base = chunk * CHUNK;
    const int nvalid = min(CHUNK, T - base);
    const int tid = threadIdx.x;

    for (int j = tid; j < nvalid; j += NTH) {
        float2 v = x[base + j];
        sd[j] = v.x - v.y;
    }
    __syncthreads();

    float a = 0.f, l = NEG_INF, h = POS_INF;
    const int j0 = tid * EPT;
#pragma unroll
    for (int jj = 0; jj < EPT; jj++) {
        int j = j0 + jj;
        if (j < nvalid) {
            float d = sd[j];
            a += d;
            l = fmaxf(l + d, 0.f);
            h = fminf(fmaxf(h + d, 0.f), smax);
        }
    }
    sa[tid] = a; sl[tid] = l; sh[tid] = h;
    __syncthreads();

    // inclusive Hillis-Steele scan (non-commutative composition)
    for (int off = 1; off < NTH; off <<= 1) {
        float pa, pl, ph;
        bool have = tid >= off;
        if (have) { pa = sa[tid - off]; pl = sl[tid - off]; ph = sh[tid - off]; }
        __syncthreads();
        if (have) {
            float ca = sa[tid], cl = sl[tid], ch = sh[tid];
            sa[tid] = pa + ca;
            sl[tid] = fmaxf(pl + ca, cl);
            sh[tid] = fminf(fmaxf(ph + ca, cl), ch);
        }
        __syncthreads();
    }
    if (tid == NTH - 1) {
        g_fa[chunk] = sa[tid];
        g_fl[chunk] = sl[tid];
        g_fh[chunk] = sh[tid];
    }
}

// ---------------------------------------------------------------------------
// K2: scan chunk clamp-functions -> S at entry of each chunk
// ---------------------------------------------------------------------------
__global__ void k2_scan_S(int NC) {
    __shared__ float sa[SCAN_TH], sl[SCAN_TH], sh[SCAN_TH];
    const int t = threadIdx.x;
    if (t < NC) { sa[t] = g_fa[t]; sl[t] = g_fl[t]; sh[t] = g_fh[t]; }
    else        { sa[t] = 0.f;     sl[t] = NEG_INF; sh[t] = POS_INF; }
    __syncthreads();
    for (int off = 1; off < SCAN_TH; off <<= 1) {
        float pa, pl, ph;
        bool have = t >= off;
        if (have) { pa = sa[t - off]; pl = sl[t - off]; ph = sh[t - off]; }
        __syncthreads();
        if (have) {
            float ca = sa[t], cl = sl[t], ch = sh[t];
            sa[t] = pa + ca;
            sl[t] = fmaxf(pl + ca, cl);
            sh[t] = fminf(fmaxf(ph + ca, cl), ch);
        }
        __syncthreads();
    }
    if (t < NC) {
        const float S0 = 0.5f;  // S_init
        g_Sin[t] = (t == 0) ? S0
                 : fminf(fmaxf(S0 + sa[t - 1], sl[t - 1]), sh[t - 1]);
    }
}

// ---------------------------------------------------------------------------
// K3: main pass. Compute per-element excess, partial totalflow (missing only
//     the (1-k)*k^j*B_in term), and the per-chunk affine (M, C) for B.
// ---------------------------------------------------------------------------
__global__ void k3_main(const float2* __restrict__ x, float* __restrict__ out,
                        int T, const float* __restrict__ pbfi,
                        const float* __restrict__ pk,
                        const float* __restrict__ psmax) {
    __shared__ float sd[CHUNK];
    __shared__ float sa[NTH], sl[NTH], sh[NTH];
    __shared__ float sm[NTH], sc[NTH];
    const float bfi = pbfi[0], k = pk[0], smax = psmax[0];
    const float omk = 1.f - k, ombfi = 1.f - bfi;
    const int chunk = blockIdx.x;
    const int base = chunk * CHUNK;
    const int nvalid = min(CHUNK, T - base);
    const int tid = threadIdx.x;

    for (int j = tid; j < nvalid; j += NTH) {
        float2 v = x[base + j];
        sd[j] = v.x - v.y;
    }
    __syncthreads();

    // 1) per-thread clamp composition
    float a = 0.f, l = NEG_INF, h = POS_INF;
    const int j0 = tid * EPT;
#pragma unroll
    for (int jj = 0; jj < EPT; jj++) {
        int j = j0 + jj;
        if (j < nvalid) {
            float d = sd[j];
            a += d;
            l = fmaxf(l + d, 0.f);
            h = fminf(fmaxf(h + d, 0.f), smax);
        }
    }
    sa[tid] = a; sl[tid] = l; sh[tid] = h;
    __syncthreads();

    // 2) block-level inclusive scan of clamp functions
    for (int off = 1; off < NTH; off <<= 1) {
        float pa, pl, ph;
        bool have = tid >= off;
        if (have) { pa = sa[tid - off]; pl = sl[tid - off]; ph = sh[tid - off]; }
        __syncthreads();
        if (have) {
            float ca = sa[tid], cl = sl[tid], ch = sh[tid];
            sa[tid] = pa + ca;
            sl[tid] = fmaxf(pl + ca, cl);
            sh[tid] = fminf(fmaxf(ph + ca, cl), ch);
        }
        __syncthreads();
    }

    // 3) S at start of this thread's segment; then compute excess sequentially,
    //    overwriting sd[] with excess; also build thread-local affine (m, c).
    float S = g_Sin[chunk];
    if (tid > 0)
        S = fminf(fmaxf(S + sa[tid - 1], sl[tid - 1]), sh[tid - 1]);

    float m = 1.f, c = 0.f;
#pragma unroll
    for (int jj = 0; jj < EPT; jj++) {
        int j = j0 + jj;
        if (j < nvalid) {
            float d = sd[j];
            S = fmaxf(S + d, 0.f);
            float e = fmaxf(S - smax, 0.f);
            S -= e;
            sd[j] = e;
            c += bfi * e;
            float bfc = omk * c;
            float bfm = omk * m;
            c -= bfc;
            m -= bfm;
        }
    }
    sm[tid] = m; sc[tid] = c;
    __syncthreads();

    // 4) block-level inclusive scan of affines (self ∘ prev): m''=m*pm, c''=m*pc+c
    for (int off = 1; off < NTH; off <<= 1) {
        float pm, pc;
        bool have = tid >= off;
        if (have) { pm = sm[tid - off]; pc = sc[tid - off]; }
        __syncthreads();
        if (have) {
            float cm = sm[tid], cc2 = sc[tid];
            sm[tid] = cm * pm;
            sc[tid] = cm * pc + cc2;
        }
        __syncthreads();
    }
    if (tid == NTH - 1) { g_M[chunk] = sm[tid]; g_C[chunk] = sc[tid]; }

    // 5) partial totals: (1-bfi)*e + (1-k)*c  (c-chain is independent of B_in)
    float cc = (tid == 0) ? 0.f : sc[tid - 1];
#pragma unroll
    for (int jj = 0; jj < EPT; jj++) {
        int j = j0 + jj;
        if (j < nvalid) {
            float e = sd[j];
            cc += bfi * e;
            float bfc = omk * cc;
            sd[j] = ombfi * e + bfc;
            cc -= bfc;
        }
    }
    __syncthreads();

    // 6) coalesced store
    for (int j = tid; j < nvalid; j += NTH)
        out[base + j] = sd[j];
}

// ---------------------------------------------------------------------------
// K4: scan per-chunk affines -> B at entry of each chunk
// ---------------------------------------------------------------------------
__global__ void k4_scan_B(int NC) {
    __shared__ float sm[SCAN_TH], sc[SCAN_TH];
    const int t = threadIdx.x;
    if (t < NC) { sm[t] = g_M[t]; sc[t] = g_C[t]; }
    else        { sm[t] = 1.f;    sc[t] = 0.f;    }
    __syncthreads();
    for (int off = 1; off < SCAN_TH; off <<= 1) {
        float pm, pc;
        bool have = t >= off;
        if (have) { pm = sm[t - off]; pc = sc[t - off]; }
        __syncthreads();
        if (have) {
            float cm = sm[t], cc = sc[t];
            sm[t] = cm * pm;
            sc[t] = cm * pc + cc;
        }
        __syncthreads();
    }
    if (t < NC) {
        const float B0 = 1.0f;  // B_init
        g_Bin[t] = (t == 0) ? B0 : sm[t - 1] * B0 + sc[t - 1];
    }
}

// ---------------------------------------------------------------------------
// K5: add the (1-k) * k^j * B_in term to the first 256 elements of each chunk
//     (k^j underflows to exactly 0 in fp32 for j >~ 150, so 256 covers all).
// ---------------------------------------------------------------------------
__global__ void k5_fix(float* __restrict__ out, int T,
                       const float* __restrict__ pk) {
    const float k = pk[0];
    const float omk = 1.f - k;
    const int chunk = blockIdx.x;
    const int j = threadIdx.x;
    const int idx = chunk * CHUNK + j;
    if (idx >= T) return;
    const float Bin = g_Bin[chunk];
    float m = 1.f;
    for (int i = 0; i < j; i++) m -= omk * m;   // mirrors reference rounding
    out[idx] += omk * m * Bin;
}

// ---------------------------------------------------------------------------
extern "C" void kernel_launch(void* const* d_in, const int* in_sizes, int n_in,
                              void* d_out, int out_size) {
    const float2* x    = (const float2*)d_in[0];
    const float*  BFI  = (const float*)d_in[1];
    const float*  K    = (const float*)d_in[2];
    const float*  Smax = (const float*)d_in[3];
    float* out = (float*)d_out;

    const int T  = in_sizes[0] / 2;
    const int NC = (T + CHUNK - 1) / CHUNK;   // 977 for T = 8e6 (<= MAX_CHUNKS)

    k1_chunk_fn<<<NC, NTH>>>(x, T, Smax);
    k2_scan_S<<<1, SCAN_TH>>>(NC);
    k3_main<<<NC, NTH>>>(x, out, T, BFI, K, Smax);
    k4_scan_B<<<1, SCAN_TH>>>(NC);
    k5_fix<<<NC, 256>>>(out, T, K);
}

// round 3
// speedup vs baseline: 1.4386x; 1.4386x over previous
#include <cuda_runtime.h>

// AWBM bucket model, single-pass decoupled-lookback scan.
//
//   S_t = min(max(S_{t-1} + d_t, 0), Smax), d = precip - evap   (clamp-add fns,
//       closed under composition -> associative scan)
//   excess_t = pre-clamp overflow
//   B_t = k*(B_{t-1} + bfi*excess_t)                             (affine scan)
//   total_t = (1-bfi)*excess_t + (1-k)*(B_{t-1} + bfi*excess_t)
//
// One main kernel: per-block clamp composition -> lookback #1 (S_in) ->
// excess + per-thread affine -> lookback #2 (B_in) -> exact per-element replay.
// A tiny reset kernel zeroes the lookback flags each launch (graph replays).

#define NTH 256
#define EPT 32
#define CHUNK (NTH * EPT)       // 8192
#define MAX_CHUNKS 1024
#define SIDX(j) ((j) + ((j) >> 5))   // bank-conflict-free padding
#define POS_INF __int_as_float(0x7f800000)
#define NEG_INF __int_as_float(0xff800000)

// lookback state (reset each launch)
__device__ volatile int   g_flag1[MAX_CHUNKS];
__device__ volatile int   g_flag2[MAX_CHUNKS];
__device__ volatile float g_agg1a[MAX_CHUNKS], g_agg1l[MAX_CHUNKS], g_agg1h[MAX_CHUNKS];
__device__ volatile float g_pre1a[MAX_CHUNKS], g_pre1l[MAX_CHUNKS], g_pre1h[MAX_CHUNKS];
__device__ volatile float g_agg2m[MAX_CHUNKS], g_agg2c[MAX_CHUNKS];
__device__ volatile float g_pre2m[MAX_CHUNKS], g_pre2c[MAX_CHUNKS];

__global__ void k_reset() {
    int t = blockIdx.x * blockDim.x + threadIdx.x;
    if (t < MAX_CHUNKS) { g_flag1[t] = 0; g_flag2[t] = 0; }
}

__global__ void __launch_bounds__(NTH)
k_main(const float4* __restrict__ x4, const float2* __restrict__ x2,
       float* __restrict__ out, int T,
       const float* __restrict__ pbfi, const float* __restrict__ pk,
       const float* __restrict__ psmax) {
    __shared__ float sd[SIDX(CHUNK - 1) + 1];
    __shared__ float sa[NTH], sl[NTH], sh[NTH];
    __shared__ float sm2[NTH], sc2[NTH];
    __shared__ float s_bcast[4];

    const float bfi = pbfi[0], k = pk[0], smax = psmax[0];
    const float ombfi = 1.f - bfi, omk = 1.f - k;
    const int c = blockIdx.x;
    const int base = c * CHUNK;
    const int nvalid = min(CHUNK, T - base);
    const int tid = threadIdx.x;
    const int j0 = tid * EPT;

    // ---- load diffs (float4 = 2 elements), coalesced, into padded smem ----
    const int n2 = nvalid >> 1;
    for (int i = tid; i < n2; i += NTH) {
        float4 v = x4[(base >> 1) + i];
        sd[SIDX(2 * i)]     = v.x - v.y;
        sd[SIDX(2 * i + 1)] = v.z - v.w;
    }
    if ((nvalid & 1) && tid == 0) {
        float2 v = x2[base + nvalid - 1];
        sd[SIDX(nvalid - 1)] = v.x - v.y;
    }
    __syncthreads();

    // ---- 1) per-thread clamp composition (conflict-free smem reads) ----
    float a = 0.f, l = NEG_INF, h = POS_INF;
#pragma unroll
    for (int jj = 0; jj < EPT; jj++) {
        int j = j0 + jj;
        if (j < nvalid) {
            float d = sd[SIDX(j)];
            a += d;
            l = fmaxf(l + d, 0.f);
            h = fminf(fmaxf(h + d, 0.f), smax);
        }
    }
    sa[tid] = a; sl[tid] = l; sh[tid] = h;
    __syncthreads();

    // ---- 2) block inclusive scan of clamp functions ----
    for (int off = 1; off < NTH; off <<= 1) {
        float pa, pl, ph;
        bool have = tid >= off;
        if (have) { pa = sa[tid - off]; pl = sl[tid - off]; ph = sh[tid - off]; }
        __syncthreads();
        if (have) {
            float ca = sa[tid], cl = sl[tid], ch = sh[tid];
            sa[tid] = pa + ca;
            sl[tid] = fmaxf(pl + ca, cl);
            sh[tid] = fminf(fmaxf(ph + ca, cl), ch);
        }
        __syncthreads();
    }

    // ---- 3) lookback phase 1: exclusive clamp prefix -> S_in ----
    if (tid == 0) {
        float Aa = sa[NTH - 1], Al = sl[NTH - 1], Ah = sh[NTH - 1];
        if (c == 0) {
            g_pre1a[0] = Aa; g_pre1l[0] = Al; g_pre1h[0] = Ah;
            __threadfence();
            g_flag1[0] = 2;
            s_bcast[0] = 0.f; s_bcast[1] = NEG_INF; s_bcast[2] = POS_INF;
        } else {
            g_agg1a[c] = Aa; g_agg1l[c] = Al; g_agg1h[c] = Ah;
            __threadfence();
            g_flag1[c] = 1;
            float La = 0.f, Ll = NEG_INF, Lh = POS_INF;  // later-applied accum
            int j = c - 1;
            for (;;) {
                int f;
                while ((f = g_flag1[j]) == 0) __nanosleep(20);
                __threadfence();
                if (f == 2) {
                    float Ea = g_pre1a[j], El = g_pre1l[j], Eh = g_pre1h[j];
                    float Pa = Ea + La;
                    float Pl = fmaxf(El + La, Ll);
                    float Ph = fminf(fmaxf(Eh + La, Ll), Lh);
                    // inclusive = own aggregate after P
                    g_pre1a[c] = Pa + Aa;
                    g_pre1l[c] = fmaxf(Pl + Aa, Al);
                    g_pre1h[c] = fminf(fmaxf(Ph + Aa, Al), Ah);
                    __threadfence();
                    g_flag1[c] = 2;
                    s_bcast[0] = Pa; s_bcast[1] = Pl; s_bcast[2] = Ph;
                    break;
                } else {
                    float Ea = g_agg1a[j], El = g_agg1l[j], Eh = g_agg1h[j];
                    float na = Ea + La;
                    float nl = fmaxf(El + La, Ll);
                    float nh = fminf(fmaxf(Eh + La, Ll), Lh);
                    La = na; Ll = nl; Lh = nh;
                    j--;
                }
            }
        }
    }
    __syncthreads();

    // S at start of this thread's segment
    float S = fminf(fmaxf(0.5f + s_bcast[0], s_bcast[1]), s_bcast[2]);  // S_init=0.5
    if (tid > 0) S = fminf(fmaxf(S + sa[tid - 1], sl[tid - 1]), sh[tid - 1]);

    // ---- 4) excess (overwrite sd) + per-thread B affine ----
    float m = 1.f, cc = 0.f;
#pragma unroll
    for (int jj = 0; jj < EPT; jj++) {
        int j = j0 + jj;
        if (j < nvalid) {
            float d = sd[SIDX(j)];
            S = fmaxf(S + d, 0.f);
            float e = fmaxf(S - smax, 0.f);
            S -= e;
            sd[SIDX(j)] = e;
            cc = cc + bfi * e;
            float bf = omk * cc; cc = cc - bf;
            float bm = omk * m;  m  = m - bm;
        }
    }
    sm2[tid] = m; sc2[tid] = cc;
    __syncthreads();

    // ---- 5) block inclusive scan of affines ----
    for (int off = 1; off < NTH; off <<= 1) {
        float pm, pc;
        bool have = tid >= off;
        if (have) { pm = sm2[tid - off]; pc = sc2[tid - off]; }
        __syncthreads();
        if (have) {
            float cm = sm2[tid], c2 = sc2[tid];
            sm2[tid] = cm * pm;
            sc2[tid] = cm * pc + c2;
        }
        __syncthreads();
    }

    // ---- 6) lookback phase 2: exclusive affine prefix -> B_in ----
    if (tid == 0) {
        float Am = sm2[NTH - 1], Ac = sc2[NTH - 1];
        if (c == 0) {
            g_pre2m[0] = Am; g_pre2c[0] = Ac;
            __threadfence();
            g_flag2[0] = 2;
            s_bcast[3] = 1.0f;                       // B_init
        } else {
            g_agg2m[c] = Am; g_agg2c[c] = Ac;
            __threadfence();
            g_flag2[c] = 1;
            float Lm = 1.f, Lc = 0.f;
            int j = c - 1;
            for (;;) {
                int f;
                while ((f = g_flag2[j]) == 0) __nanosleep(20);
                __threadfence();
                if (f == 2) {
                    float Em = g_pre2m[j], Ec = g_pre2c[j];
                    float Pm = Lm * Em;
                    float Pc = Lm * Ec + Lc;
                    g_pre2m[c] = Am * Pm;
                    g_pre2c[c] = Am * Pc + Ac;
                    __threadfence();
                    g_flag2[c] = 2;
                    s_bcast[3] = Pm * 1.0f + Pc;     // B_in = P(B_init)
                    break;
                } else {
                    float Em = g_agg2m[j], Ec = g_agg2c[j];
                    float nm = Lm * Em;
                    float nc = Lm * Ec + Lc;
                    Lm = nm; Lc = nc;
                    j--;
                }
            }
        }
    }
    __syncthreads();

    float B = s_bcast[3];
    if (tid > 0) B = sm2[tid - 1] * B + sc2[tid - 1];

    // ---- 7) exact reference replay per element; totals into sd ----
#pragma unroll
    for (int jj = 0; jj < EPT; jj++) {
        int j = j0 + jj;
        if (j < nvalid) {
            float e = sd[SIDX(j)];
            float outflow = ombfi * e;
            B = B + bfi * e;
            float baseflow = omk * B;
            B = B - baseflow;
            sd[SIDX(j)] = outflow + baseflow;
        }
    }
    __syncthreads();

    // ---- 8) coalesced store (float4 fast path) ----
    const int n4o = nvalid >> 2;
    float4* out4 = (float4*)(out + base);
    for (int i = tid; i < n4o; i += NTH) {
        float4 v;
        v.x = sd[SIDX(4 * i)];
        v.y = sd[SIDX(4 * i + 1)];
        v.z = sd[SIDX(4 * i + 2)];
        v.w = sd[SIDX(4 * i + 3)];
        out4[i] = v;
    }
    for (int j = (n4o << 2) + tid; j < nvalid; j += NTH)
        out[base + j] = sd[SIDX(j)];
}

extern "C" void kernel_launch(void* const* d_in, const int* in_sizes, int n_in,
                              void* d_out, int out_size) {
    const float4* x4   = (const float4*)d_in[0];
    const float2* x2   = (const float2*)d_in[0];
    const float*  BFI  = (const float*)d_in[1];
    const float*  K    = (const float*)d_in[2];
    const float*  Smax = (const float*)d_in[3];
    float* out = (float*)d_out;

    const int T  = in_sizes[0] / 2;
    const int NC = (T + CHUNK - 1) / CHUNK;   // 977 for T = 8e6

    k_reset<<<(MAX_CHUNKS + 255) / 256, 256>>>();
    k_main<<<NC, NTH>>>(x4, x2, out, T, BFI, K, Smax);
}

// round 5
// speedup vs baseline: 5.9149x; 4.1114x over previous
#include <cuda_runtime.h>

// AWBM bucket model, single-pass decoupled lookback with WARP-PARALLEL lookback
// (CUB-style): 32 predecessor tile-states polled per L2 round trip, packed as
// one uint4 {flag, payload0, payload1, payload2} so flag+payload arrive in a
// single 128-bit transaction.
//
//   S_t   = min(max(S_{t-1}+d_t,0),Smax)   clamp-add fns, closed under composition
//   e_t   = pre-clamp overflow
//   B_t   = k*(B_{t-1}+bfi*e_t)            affine
//   out_t = (1-bfi)*e_t + (1-k)*(B_{t-1}+bfi*e_t)

#define NTH 256
#define EPT 32
#define CHUNK (NTH * EPT)       // 8192
#define MAX_CHUNKS 1024
#define SIDX(j) ((j) + ((j) >> 5))
#define POS_INF __int_as_float(0x7f800000)
#define NEG_INF __int_as_float(0xff800000)
#define FULL 0xffffffffu

// per-tile lookback state: {flag(0/1/2), f0, f1, f2}
__device__ uint4 g_st1[MAX_CHUNKS];   // clamp fn (a, l, h)
__device__ uint4 g_st2[MAX_CHUNKS];   // affine   (m, c, -)

struct Fn  { float a, l, h; };        // x -> min(max(x+a, l), h)
struct Aff { float m, c; };           // x -> m*x + c

__device__ __forceinline__ Fn fn_id() { Fn f; f.a = 0.f; f.l = NEG_INF; f.h = POS_INF; return f; }
__device__ __forceinline__ Fn fn_comb(Fn p, Fn n) {   // p first, then n
    Fn r;
    r.a = p.a + n.a;
    r.l = fmaxf(p.l + n.a, n.l);
    r.h = fminf(fmaxf(p.h + n.a, n.l), n.h);
    return r;
}
__device__ __forceinline__ float fn_apply(Fn f, float x) {
    return fminf(fmaxf(x + f.a, f.l), f.h);
}
__device__ __forceinline__ Aff af_id() { Aff a; a.m = 1.f; a.c = 0.f; return a; }
__device__ __forceinline__ Aff af_comb(Aff p, Aff n) {
    Aff r; r.m = n.m * p.m; r.c = n.m * p.c + n.c; return r;
}

__device__ __forceinline__ uint4 ldv4(const uint4* p) {
    uint4 v;
    asm volatile("ld.volatile.global.v4.b32 {%0,%1,%2,%3}, [%4];"
                 : "=r"(v.x), "=r"(v.y), "=r"(v.z), "=r"(v.w) : "l"(p) : "memory");
    return v;
}
__device__ __forceinline__ void stv4(uint4* p, uint4 v) {
    asm volatile("st.volatile.global.v4.b32 [%0], {%1,%2,%3,%4};"
                 :: "l"(p), "r"(v.x), "r"(v.y), "r"(v.z), "r"(v.w) : "memory");
}

__global__ void k_reset() {
    int t = blockIdx.x * blockDim.x + threadIdx.x;
    if (t < MAX_CHUNKS) {
        uint4 z; z.x = 0; z.y = 0; z.z = 0; z.w = 0;
        stv4(&g_st1[t], z);
        stv4(&g_st2[t], z);
    }
}

// warp-parallel lookback, phase 1 (clamp fns). Whole warp calls; returns the
// exclusive prefix (composition of tiles 0..c-1), valid on all lanes.
__device__ Fn lookback1(int c, int lane) {
    Fn L = fn_id();              // composition of already-consumed later tiles
    int whi = c - 1;
    for (;;) {
        int wlo = whi - 31; if (wlo < 0) wlo = 0;
        int n = whi - wlo + 1;
        uint4 st; int flag;
        for (;;) {
            flag = 1;
            if (lane < n) { st = ldv4(&g_st1[wlo + lane]); flag = (int)st.x; }
            if (__all_sync(FULL, flag != 0)) break;
            __nanosleep(40);
        }
        Fn v = fn_id();
        if (lane < n) { v.a = __uint_as_float(st.y); v.l = __uint_as_float(st.z); v.h = __uint_as_float(st.w); }
        unsigned pm = __ballot_sync(FULL, (lane < n) && (flag == 2));
        int P = pm ? (31 - __clz(pm)) : -1;
        if (P >= 0 && lane < P) v = fn_id();   // prefix at P already covers them
        // ascending inclusive warp scan (lower lanes applied first)
        Fn s = v;
#pragma unroll
        for (int off = 1; off < 32; off <<= 1) {
            Fn up;
            up.a = __shfl_up_sync(FULL, s.a, off);
            up.l = __shfl_up_sync(FULL, s.l, off);
            up.h = __shfl_up_sync(FULL, s.h, off);
            if (lane >= off) s = fn_comb(up, s);
        }
        Fn W;
        W.a = __shfl_sync(FULL, s.a, n - 1);
        W.l = __shfl_sync(FULL, s.l, n - 1);
        W.h = __shfl_sync(FULL, s.h, n - 1);
        Fn newL = fn_comb(W, L);
        if (P >= 0) return newL;
        L = newL;
        whi = wlo - 1;
    }
}

__device__ Aff lookback2(int c, int lane) {
    Aff L = af_id();
    int whi = c - 1;
    for (;;) {
        int wlo = whi - 31; if (wlo < 0) wlo = 0;
        int n = whi - wlo + 1;
        uint4 st; int flag;
        for (;;) {
            flag = 1;
            if (lane < n) { st = ldv4(&g_st2[wlo + lane]); flag = (int)st.x; }
            if (__all_sync(FULL, flag != 0)) break;
            __nanosleep(40);
        }
        Aff v = af_id();
        if (lane < n) { v.m = __uint_as_float(st.y); v.c = __uint_as_float(st.z); }
        unsigned pm = __ballot_sync(FULL, (lane < n) && (flag == 2));
        int P = pm ? (31 - __clz(pm)) : -1;
        if (P >= 0 && lane < P) v = af_id();
        Aff s = v;
#pragma unroll
        for (int off = 1; off < 32; off <<= 1) {
            Aff up;
            up.m = __shfl_up_sync(FULL, s.m, off);
            up.c = __shfl_up_sync(FULL, s.c, off);
            if (lane >= off) s = af_comb(up, s);
        }
        Aff W;
        W.m = __shfl_sync(FULL, s.m, n - 1);
        W.c = __shfl_sync(FULL, s.c, n - 1);
        Aff newL = af_comb(W, L);
        if (P >= 0) return newL;
        L = newL;
        whi = wlo - 1;
    }
}

__global__ void __launch_bounds__(NTH)
k_main(const float4* __restrict__ x4, const float2* __restrict__ x2,
       float* __restrict__ out, int T,
       const float* __restrict__ pbfi, const float* __restrict__ pk,
       const float* __restrict__ psmax) {
    __shared__ float sd[SIDX(CHUNK - 1) + 1];
    __shared__ float swa[8], swl[8], swh[8];     // warp fn aggregates / prefixes
    __shared__ float swm[8], swc[8];             // warp affine aggregates / prefixes
    __shared__ float s_bc[2];                    // S_in, B_in

    const float bfi = pbfi[0], k = pk[0], smax = psmax[0];
    const float ombfi = 1.f - bfi, omk = 1.f - k;
    const int c = blockIdx.x;
    const int base = c * CHUNK;
    const int nvalid = min(CHUNK, T - base);
    const int tid = threadIdx.x;
    const int lane = tid & 31;
    const int w = tid >> 5;
    const int j0 = tid * EPT;

    // ---- load diffs into padded smem (float4 = 2 timesteps) ----
    const int n2 = nvalid >> 1;
    for (int i = tid; i < n2; i += NTH) {
        float4 v = x4[(base >> 1) + i];
        sd[SIDX(2 * i)]     = v.x - v.y;
        sd[SIDX(2 * i + 1)] = v.z - v.w;
    }
    if ((nvalid & 1) && tid == 0) {
        float2 v = x2[base + nvalid - 1];
        sd[SIDX(nvalid - 1)] = v.x - v.y;
    }
    __syncthreads();

    // ---- 1) per-thread clamp composition ----
    Fn f = fn_id();
#pragma unroll
    for (int jj = 0; jj < EPT; jj++) {
        int j = j0 + jj;
        if (j < nvalid) {
            float d = sd[SIDX(j)];
            f.a += d;
            f.l = fmaxf(f.l + d, 0.f);
            f.h = fminf(fmaxf(f.h + d, 0.f), smax);
        }
    }

    // ---- 2) warp inclusive scan (shuffle) ----
    Fn finc = f;
#pragma unroll
    for (int off = 1; off < 32; off <<= 1) {
        Fn up;
        up.a = __shfl_up_sync(FULL, finc.a, off);
        up.l = __shfl_up_sync(FULL, finc.l, off);
        up.h = __shfl_up_sync(FULL, finc.h, off);
        if (lane >= off) finc = fn_comb(up, finc);
    }
    if (lane == 31) { swa[w] = finc.a; swl[w] = finc.l; swh[w] = finc.h; }
    __syncthreads();

    // ---- 3) warp 0: combine 8 warp aggregates, publish, lookback ----
    if (w == 0) {
        Fn wa = fn_id();
        if (lane < 8) { wa.a = swa[lane]; wa.l = swl[lane]; wa.h = swh[lane]; }
        Fn wsc = wa;
#pragma unroll
        for (int off = 1; off < 8; off <<= 1) {
            Fn up;
            up.a = __shfl_up_sync(FULL, wsc.a, off);
            up.l = __shfl_up_sync(FULL, wsc.l, off);
            up.h = __shfl_up_sync(FULL, wsc.h, off);
            if (lane >= off) wsc = fn_comb(up, wsc);
        }
        if (lane < 8) { swa[lane] = wsc.a; swl[lane] = wsc.l; swh[lane] = wsc.h; }
        Fn agg;
        agg.a = __shfl_sync(FULL, wsc.a, 7);
        agg.l = __shfl_sync(FULL, wsc.l, 7);
        agg.h = __shfl_sync(FULL, wsc.h, 7);
        // publish aggregate (flag 1) or, for tile 0, prefix (flag 2) right away
        if (lane == 0) {
            uint4 s;
            s.x = (c == 0) ? 2u : 1u;
            s.y = __float_as_uint(agg.a); s.z = __float_as_uint(agg.l); s.w = __float_as_uint(agg.h);
            stv4(&g_st1[c], s);
        }
        Fn pre = fn_id();
        if (c > 0) {
            pre = lookback1(c, lane);
            if (lane == 0) {
                Fn inc = fn_comb(pre, agg);
                uint4 s;
                s.x = 2u;
                s.y = __float_as_uint(inc.a); s.z = __float_as_uint(inc.l); s.w = __float_as_uint(inc.h);
                stv4(&g_st1[c], s);
            }
        }
        if (lane == 0) s_bc[0] = fn_apply(pre, 0.5f);   // S_init = 0.5
    }
    __syncthreads();

    // ---- 4) per-thread start S, then excess + thread affine ----
    float S = s_bc[0];
    {
        Fn wex = fn_id();
        if (w > 0) { wex.a = swa[w - 1]; wex.l = swl[w - 1]; wex.h = swh[w - 1]; }
        Fn lex;
        lex.a = __shfl_up_sync(FULL, finc.a, 1);
        lex.l = __shfl_up_sync(FULL, finc.l, 1);
        lex.h = __shfl_up_sync(FULL, finc.h, 1);
        if (lane == 0) lex = fn_id();
        Fn tex = fn_comb(wex, lex);
        S = fn_apply(tex, S);
    }

    Aff af = af_id();
#pragma unroll
    for (int jj = 0; jj < EPT; jj++) {
        int j = j0 + jj;
        if (j < nvalid) {
            float d = sd[SIDX(j)];
            S = fmaxf(S + d, 0.f);
            float e = fmaxf(S - smax, 0.f);
            S -= e;
            sd[SIDX(j)] = e;
            af.c = af.c + bfi * e;
            float bf = omk * af.c; af.c = af.c - bf;
            float bm = omk * af.m; af.m = af.m - bm;
        }
    }

    // ---- 5) warp scan of affines ----
    Aff ainc = af;
#pragma unroll
    for (int off = 1; off < 32; off <<= 1) {
        Aff up;
        up.m = __shfl_up_sync(FULL, ainc.m, off);
        up.c = __shfl_up_sync(FULL, ainc.c, off);
        if (lane >= off) ainc = af_comb(up, ainc);
    }
    if (lane == 31) { swm[w] = ainc.m; swc[w] = ainc.c; }
    __syncthreads();

    // ---- 6) warp 0: combine, publish, lookback #2 ----
    if (w == 0) {
        Aff wa = af_id();
        if (lane < 8) { wa.m = swm[lane]; wa.c = swc[lane]; }
        Aff wsc = wa;
#pragma unroll
        for (int off = 1; off < 8; off <<= 1) {
            Aff up;
            up.m = __shfl_up_sync(FULL, wsc.m, off);
            up.c = __shfl_up_sync(FULL, wsc.c, off);
            if (lane >= off) wsc = af_comb(up, wsc);
        }
        if (lane < 8) { swm[lane] = wsc.m; swc[lane] = wsc.c; }
        Aff agg;
        agg.m = __shfl_sync(FULL, wsc.m, 7);
        agg.c = __shfl_sync(FULL, wsc.c, 7);
        if (lane == 0) {
            uint4 s;
            s.x = (c == 0) ? 2u : 1u;
            s.y = __float_as_uint(agg.m); s.z = __float_as_uint(agg.c); s.w = 0u;
            stv4(&g_st2[c], s);
        }
        Aff pre = af_id();
        if (c > 0) {
            pre = lookback2(c, lane);
            if (lane == 0) {
                Aff inc = af_comb(pre, agg);
                uint4 s;
                s.x = 2u;
                s.y = __float_as_uint(inc.m); s.z = __float_as_uint(inc.c); s.w = 0u;
                stv4(&g_st2[c], s);
            }
        }
        if (lane == 0) s_bc[1] = pre.m * 1.0f + pre.c;   // B_init = 1
    }
    __syncthreads();

    // ---- 7) per-thread start B, exact reference replay ----
    float B = s_bc[1];
    {
        Aff wex = af_id();
        if (w > 0) { wex.m = swm[w - 1]; wex.c = swc[w - 1]; }
        Aff lex;
        lex.m = __shfl_up_sync(FULL, ainc.m, 1);
        lex.c = __shfl_up_sync(FULL, ainc.c, 1);
        if (lane == 0) lex = af_id();
        Aff tex = af_comb(wex, lex);
        B = tex.m * B + tex.c;
    }
#pragma unroll
    for (int jj = 0; jj < EPT; jj++) {
        int j = j0 + jj;
        if (j < nvalid) {
            float e = sd[SIDX(j)];
            float outflow = ombfi * e;
            B = B + bfi * e;
            float baseflow = omk * B;
            B = B - baseflow;
            sd[SIDX(j)] = outflow + baseflow;
        }
    }
    __syncthreads();

    // ---- 8) coalesced float4 store ----
    const int n4o = nvalid >> 2;
    float4* out4 = (float4*)(out + base);
    for (int i = tid; i < n4o; i += NTH) {
        float4 v;
        v.x = sd[SIDX(4 * i)];
        v.y = sd[SIDX(4 * i + 1)];
        v.z = sd[SIDX(4 * i + 2)];
        v.w = sd[SIDX(4 * i + 3)];
        out4[i] = v;
    }
    for (int j = (n4o << 2) + tid; j < nvalid; j += NTH)
        out[base + j] = sd[SIDX(j)];
}

extern "C" void kernel_launch(void* const* d_in, const int* in_sizes, int n_in,
                              void* d_out, int out_size) {
    const float4* x4   = (const float4*)d_in[0];
    const float2* x2   = (const float2*)d_in[0];
    const float*  BFI  = (const float*)d_in[1];
    const float*  K    = (const float*)d_in[2];
    const float*  Smax = (const float*)d_in[3];
    float* out = (float*)d_out;

    const int T  = in_sizes[0] / 2;
    const int NC = (T + CHUNK - 1) / CHUNK;   // 977 for T = 8e6

    k_reset<<<(MAX_CHUNKS + 255) / 256, 256>>>();
    k_main<<<NC, NTH>>>(x4, x2, out, T, BFI, K, Smax);
}